// round 6
// baseline (speedup 1.0000x reference)
#include <cuda_runtime.h>
#include <math.h>

#define NFFT 16384
#define LOGN 14
#define BROWS 512
#define FFT_THREADS 1024

// accumulators: 0=sum(1-pear), 1=sum cos, 2=sum|xp-tp|, 3=sum tp, 4=sum nmi
__device__ double g_acc[5];
__device__ float2 g_tw[NFFT / 2];   // exp(-2*pi*i*t/N), double-precision generated

// ---------------------------------------------------------------- init
__global__ void init_kernel() {
    int t = blockIdx.x * blockDim.x + threadIdx.x;
    if (t < 5) g_acc[t] = 0.0;
    if (t < NFFT / 2) {
        double s, c;
        sincospi(-2.0 * (double)t / (double)NFFT, &s, &c);
        g_tw[t] = make_float2((float)c, (float)s);
    }
}

// ---------------------------------------------------------------- helpers
__device__ __forceinline__ double blockReduceSumD(double v, double* s) {
    for (int o = 16; o > 0; o >>= 1) v += __shfl_down_sync(0xffffffffu, v, o);
    int lane = threadIdx.x & 31, w = threadIdx.x >> 5;
    __syncthreads();                       // protect smem reuse across calls
    if (lane == 0) s[w] = v;
    __syncthreads();
    if (threadIdx.x == 0) {
        int nw = blockDim.x >> 5;
        double r = s[0];
        for (int i = 1; i < nw; i++) r += s[i];
        v = r;
    }
    return v;  // valid on thread 0
}

__device__ __forceinline__ float blockMinAll(float v, float* s) {
    for (int o = 16; o > 0; o >>= 1) v = fminf(v, __shfl_down_sync(0xffffffffu, v, o));
    int lane = threadIdx.x & 31, w = threadIdx.x >> 5;
    __syncthreads();
    if (lane == 0) s[w] = v;
    __syncthreads();
    if (threadIdx.x == 0) {
        int nw = blockDim.x >> 5;
        float r = s[0];
        for (int i = 1; i < nw; i++) r = fminf(r, s[i]);
        s[0] = r;
    }
    __syncthreads();
    float r = s[0];
    __syncthreads();
    return r;
}

__device__ __forceinline__ float blockMaxAll(float v, float* s) {
    for (int o = 16; o > 0; o >>= 1) v = fmaxf(v, __shfl_down_sync(0xffffffffu, v, o));
    int lane = threadIdx.x & 31, w = threadIdx.x >> 5;
    __syncthreads();
    if (lane == 0) s[w] = v;
    __syncthreads();
    if (threadIdx.x == 0) {
        int nw = blockDim.x >> 5;
        float r = s[0];
        for (int i = 1; i < nw; i++) r = fmaxf(r, s[i]);
        s[0] = r;
    }
    __syncthreads();
    float r = s[0];
    __syncthreads();
    return r;
}

__device__ __forceinline__ float2 cmul(float2 a, float2 b) {
    return make_float2(a.x * b.x - a.y * b.y, a.x * b.y + a.y * b.x);
}

// ---------------------------------------------------------------- pearson
__global__ void __launch_bounds__(256) pearson_kernel(const float* __restrict__ pred,
                                                      const float* __restrict__ targ,
                                                      const int* __restrict__ ip) {
    int row = blockIdx.x;
    const float* x = pred + (size_t)ip[0] * BROWS * NFFT + (size_t)row * NFFT;
    const float* y = targ + (size_t)row * NFFT;
    double sx = 0, sy = 0, sxy = 0, sx2 = 0, sy2 = 0;
    for (int n = threadIdx.x; n < NFFT; n += blockDim.x) {
        double a = x[n], b = y[n];
        sx += a; sy += b; sxy += a * b; sx2 += a * a; sy2 += b * b;
    }
    __shared__ double red[32];
    double rsx  = blockReduceSumD(sx, red);
    double rsy  = blockReduceSumD(sy, red);
    double rsxy = blockReduceSumD(sxy, red);
    double rsx2 = blockReduceSumD(sx2, red);
    double rsy2 = blockReduceSumD(sy2, red);
    if (threadIdx.x == 0) {
        double Nd = (double)NFFT;
        double num = Nd * rsxy - rsx * rsy;
        double den = sqrt((Nd * rsx2 - rsx * rsx) * (Nd * rsy2 - rsy * rsy));
        atomicAdd(&g_acc[0], 1.0 - num / den);
    }
}

// ---------------------------------------------------------------- mutual information
__global__ void __launch_bounds__(256) mi_kernel(const float* __restrict__ pred,
                                                 const float* __restrict__ targ,
                                                 const int* __restrict__ ip) {
    int row = blockIdx.x;
    const float* x = pred + (size_t)ip[0] * BROWS * NFFT + (size_t)row * NFFT;
    const float* y = targ + (size_t)row * NFFT;
    __shared__ float sred[32];
    __shared__ int hist[100];

    float xmn = 1e30f, xmx = -1e30f, ymn = 1e30f, ymx = -1e30f;
    for (int n = threadIdx.x; n < NFFT; n += blockDim.x) {
        float a = x[n], b = y[n];
        xmn = fminf(xmn, a); xmx = fmaxf(xmx, a);
        ymn = fminf(ymn, b); ymx = fmaxf(ymx, b);
    }
    xmn = blockMinAll(xmn, sred);
    xmx = blockMaxAll(xmx, sred);
    ymn = blockMinAll(ymn, sred);
    ymx = blockMaxAll(ymx, sred);

    float bwx = (xmx - xmn) / 10.0f;
    float bwy = (ymx - ymn) / 10.0f;

    for (int t = threadIdx.x; t < 100; t += blockDim.x) hist[t] = 0;
    __syncthreads();
    for (int n = threadIdx.x; n < NFFT; n += blockDim.x) {
        int ix = (int)((x[n] - xmn) / bwx);
        int iy = (int)((y[n] - ymn) / bwy);
        ix = min(max(ix, 0), 9);
        iy = min(max(iy, 0), 9);
        atomicAdd(&hist[ix * 10 + iy], 1);
    }
    __syncthreads();

    if (threadIdx.x == 0) {
        const double denom = (double)BROWS * (double)NFFT;
        const double eps = 1e-8;
        double hx[10], hy[10];
        for (int j = 0; j < 10; j++) { hx[j] = 0; hy[j] = 0; }
        for (int j = 0; j < 10; j++)
            for (int k = 0; k < 10; k++) {
                double h = (double)hist[j * 10 + k];
                hx[j] += h; hy[k] += h;
            }
        double mi = 0;
        for (int j = 0; j < 10; j++)
            for (int k = 0; k < 10; k++) {
                double pxy = (double)hist[j * 10 + k] / denom;
                double px = hx[j] / denom, py = hy[k] / denom;
                mi += pxy * log((pxy + eps) / (px * py + eps));
            }
        double hxe = 0, hye = 0;
        for (int j = 0; j < 10; j++) {
            double px = hx[j] / denom, py = hy[j] / denom;
            hxe -= px * log(px + eps);
            hye -= py * log(py + eps);
        }
        double nmi = mi / ((hxe + hye) * 0.5);
        atomicAdd(&g_acc[4], nmi);
    }
}

// ---------------------------------------------------------------- FFT (in shared mem)
__device__ void fft_inplace(float2* d) {
    int tid = threadIdx.x;
    // bit-reversal permutation
    for (int idx = tid; idx < NFFT; idx += FFT_THREADS) {
        int r = __brev((unsigned)idx) >> (32 - LOGN);
        if (r > idx) { float2 tmp = d[idx]; d[idx] = d[r]; d[r] = tmp; }
    }
    __syncthreads();
    for (int s = 1; s <= LOGN; s++) {
        int half = 1 << (s - 1);
        int step = NFFT >> s;
#pragma unroll 1
        for (int b = tid; b < NFFT / 2; b += FFT_THREADS) {
            int j = b & (half - 1);
            int k1 = ((b >> (s - 1)) << s) + j;
            int k2 = k1 + half;
            float2 w = g_tw[j * step];
            float2 a = d[k1];
            float2 t = cmul(d[k2], w);
            d[k1] = make_float2(a.x + t.x, a.y + t.y);
            d[k2] = make_float2(a.x - t.x, a.y - t.y);
        }
        __syncthreads();
    }
}

// ---------------------------------------------------------------- spectral terms
extern __shared__ float2 sdata[];

__global__ void __launch_bounds__(FFT_THREADS, 1)
spectral_kernel(const float* __restrict__ pred, const float* __restrict__ targ,
                const int* __restrict__ ip) {
    int row = blockIdx.x;
    const float* x = pred + (size_t)ip[0] * BROWS * NFFT + (size_t)row * NFFT;
    const float* y = targ + (size_t)row * NFFT;
    int tid = threadIdx.x;
    __shared__ double red[32];

    // ===== power spectrum: one complex FFT of z = x + i*t =====
    for (int n = tid; n < NFFT; n += FFT_THREADS)
        sdata[n] = make_float2(x[n], y[n]);
    __syncthreads();
    fft_inplace(sdata);
    double la = 0, lt = 0;
    for (int k = tid; k <= NFFT / 2; k += FFT_THREADS) {
        float2 Zk = sdata[k];
        float2 Zm = sdata[(NFFT - k) & (NFFT - 1)];
        float xr = 0.5f * (Zk.x + Zm.x), xi = 0.5f * (Zk.y - Zm.y);
        float yr = 0.5f * (Zk.y + Zm.y), yi = 0.5f * (Zm.x - Zk.x);
        float xp = xr * xr + xi * xi;
        float tp = yr * yr + yi * yi;
        la += fabsf(xp - tp);
        lt += tp;
    }
    double ba = blockReduceSumD(la, red);
    double bt = blockReduceSumD(lt, red);
    if (tid == 0) { atomicAdd(&g_acc[2], ba); atomicAdd(&g_acc[3], bt); }
    __syncthreads();

    // ===== phase correlation: windowed FFT, phase-only corr, inverse FFT, argmax =====
    const float invN = 1.0f / (float)NFFT;
    for (int n = tid; n < NFFT; n += FFT_THREADS) {
        float w = 0.5f * (1.0f - cospif(2.0f * (float)n * invN));
        sdata[n] = make_float2(x[n] * w, y[n] * w);
    }
    __syncthreads();
    fft_inplace(sdata);
    // build D = conj(full phase-correlation spectrum) in place; each pair (k, N-k)
    // is owned by exactly one thread -> no barrier needed inside the loop
    for (int k = tid; k <= NFFT / 2; k += FFT_THREADS) {
        int km = (NFFT - k) & (NFFT - 1);
        float2 Zk = sdata[k];
        float2 Zm = sdata[km];
        float xr = 0.5f * (Zk.x + Zm.x), xi = 0.5f * (Zk.y - Zm.y);
        float yr = 0.5f * (Zk.y + Zm.y), yi = 0.5f * (Zm.x - Zk.x);
        float cr = xr * yr + xi * yi;       // C = X * conj(T)
        float ci = xi * yr - xr * yi;
        float inv = rsqrtf(cr * cr + ci * ci);
        cr *= inv; ci *= inv;
        sdata[k] = make_float2(cr, -ci);    // D[k]   = conj(Chat)
        if (km != k) sdata[km] = make_float2(cr, ci);  // D[N-k] = Chat
    }
    __syncthreads();
    fft_inplace(sdata);   // irfft(Chat) ~ Re(result)/N ; argmax unaffected by 1/N
    float bv = -1e30f; int bi = 0;
    for (int n = tid; n < NFFT; n += FFT_THREADS) {
        float v = sdata[n].x;
        if (v > bv) { bv = v; bi = n; }     // strided scan keeps first-index within thread
    }
    __shared__ float sv[32];
    __shared__ int si[32];
    int lane = tid & 31, w = tid >> 5;
    for (int o = 16; o > 0; o >>= 1) {
        float ov = __shfl_down_sync(0xffffffffu, bv, o);
        int   oi = __shfl_down_sync(0xffffffffu, bi, o);
        if (ov > bv || (ov == bv && oi < bi)) { bv = ov; bi = oi; }
    }
    if (lane == 0) { sv[w] = bv; si[w] = bi; }
    __syncthreads();
    if (tid == 0) {
        int nw = FFT_THREADS >> 5;
        for (int iw = 1; iw < nw; iw++)
            if (sv[iw] > bv || (sv[iw] == bv && si[iw] < bi)) { bv = sv[iw]; bi = si[iw]; }
        atomicAdd(&g_acc[1], cospi(2.0 * (double)bi / (double)NFFT));
    }
}

// ---------------------------------------------------------------- finalize
__global__ void finalize_kernel(const int* __restrict__ ep, float* __restrict__ out) {
    double loss = g_acc[0] / (double)BROWS;          // neg pearson
    int epoch = ep[0];
    if (epoch >= 400) {
        loss += 1.0 - g_acc[1] / (double)BROWS;      // phase correlation
        loss += g_acc[2] / g_acc[3];                 // power spectrum
    }
    if (epoch >= 700) {
        loss += 1.0 - g_acc[4] / (double)BROWS;      // mutual information
    }
    out[0] = (float)loss;
}

// ---------------------------------------------------------------- launch
extern "C" void kernel_launch(void* const* d_in, const int* in_sizes, int n_in,
                              void* d_out, int out_size) {
    const float* pred = (const float*)d_in[0];   // [2, 512, 16384] f32
    const float* targ = (const float*)d_in[1];   // [512, 16384] f32
    const int* ip = (const int*)d_in[2];         // scalar i
    const int* ep = (const int*)d_in[3];         // scalar epoch
    float* out = (float*)d_out;

    cudaFuncSetAttribute(spectral_kernel,
                         cudaFuncAttributeMaxDynamicSharedMemorySize,
                         NFFT * (int)sizeof(float2));

    init_kernel<<<32, 256>>>();                                  // 8192 threads
    pearson_kernel<<<BROWS, 256>>>(pred, targ, ip);
    mi_kernel<<<BROWS, 256>>>(pred, targ, ip);
    spectral_kernel<<<BROWS, FFT_THREADS, NFFT * sizeof(float2)>>>(pred, targ, ip);
    finalize_kernel<<<1, 1>>>(ep, out);
}

// round 9
// speedup vs baseline: 1.0553x; 1.0553x over previous
#include <cuda_runtime.h>
#include <math.h>

#define NFFT 16384
#define LOGN 14
#define BROWS 512
#define FFT_THREADS 1024

// accumulators: 0=sum(1-pear), 1=sum cos, 2=sum|xp-tp|, 3=sum tp, 4=sum nmi
__device__ double g_acc[5];
__device__ float2 g_tw[NFFT / 2];   // exp(-2*pi*i*t/N), double-precision generated

// ---------------------------------------------------------------- init
__global__ void init_kernel() {
    int t = blockIdx.x * blockDim.x + threadIdx.x;
    if (t < 5) g_acc[t] = 0.0;
    if (t < NFFT / 2) {
        double s, c;
        sincospi(-2.0 * (double)t / (double)NFFT, &s, &c);
        g_tw[t] = make_float2((float)c, (float)s);
    }
}

// ---------------------------------------------------------------- helpers
__device__ __forceinline__ double blockReduceSumD(double v, double* s) {
    for (int o = 16; o > 0; o >>= 1) v += __shfl_down_sync(0xffffffffu, v, o);
    int lane = threadIdx.x & 31, w = threadIdx.x >> 5;
    __syncthreads();                       // protect smem reuse across calls
    if (lane == 0) s[w] = v;
    __syncthreads();
    if (threadIdx.x == 0) {
        int nw = blockDim.x >> 5;
        double r = s[0];
        for (int i = 1; i < nw; i++) r += s[i];
        v = r;
    }
    return v;  // valid on thread 0
}

__device__ __forceinline__ float blockMinAll(float v, float* s) {
    for (int o = 16; o > 0; o >>= 1) v = fminf(v, __shfl_down_sync(0xffffffffu, v, o));
    int lane = threadIdx.x & 31, w = threadIdx.x >> 5;
    __syncthreads();
    if (lane == 0) s[w] = v;
    __syncthreads();
    if (threadIdx.x == 0) {
        int nw = blockDim.x >> 5;
        float r = s[0];
        for (int i = 1; i < nw; i++) r = fminf(r, s[i]);
        s[0] = r;
    }
    __syncthreads();
    float r = s[0];
    __syncthreads();
    return r;
}

__device__ __forceinline__ float blockMaxAll(float v, float* s) {
    for (int o = 16; o > 0; o >>= 1) v = fmaxf(v, __shfl_down_sync(0xffffffffu, v, o));
    int lane = threadIdx.x & 31, w = threadIdx.x >> 5;
    __syncthreads();
    if (lane == 0) s[w] = v;
    __syncthreads();
    if (threadIdx.x == 0) {
        int nw = blockDim.x >> 5;
        float r = s[0];
        for (int i = 1; i < nw; i++) r = fmaxf(r, s[i]);
        s[0] = r;
    }
    __syncthreads();
    float r = s[0];
    __syncthreads();
    return r;
}

__device__ __forceinline__ float2 cmul(float2 a, float2 b) {
    return make_float2(a.x * b.x - a.y * b.y, a.x * b.y + a.y * b.x);
}

// ---------------------------------------------------------------- pearson
__global__ void __launch_bounds__(256) pearson_kernel(const float* __restrict__ pred,
                                                      const float* __restrict__ targ,
                                                      const int* __restrict__ ip) {
    int row = blockIdx.x;
    const float* x = pred + (size_t)ip[0] * BROWS * NFFT + (size_t)row * NFFT;
    const float* y = targ + (size_t)row * NFFT;
    double sx = 0, sy = 0, sxy = 0, sx2 = 0, sy2 = 0;
    for (int n = threadIdx.x; n < NFFT; n += blockDim.x) {
        double a = x[n], b = y[n];
        sx += a; sy += b; sxy += a * b; sx2 += a * a; sy2 += b * b;
    }
    __shared__ double red[32];
    double rsx  = blockReduceSumD(sx, red);
    double rsy  = blockReduceSumD(sy, red);
    double rsxy = blockReduceSumD(sxy, red);
    double rsx2 = blockReduceSumD(sx2, red);
    double rsy2 = blockReduceSumD(sy2, red);
    if (threadIdx.x == 0) {
        double Nd = (double)NFFT;
        double num = Nd * rsxy - rsx * rsy;
        double den = sqrt((Nd * rsx2 - rsx * rsx) * (Nd * rsy2 - rsy * rsy));
        atomicAdd(&g_acc[0], 1.0 - num / den);
    }
}

// ---------------------------------------------------------------- mutual information
__global__ void __launch_bounds__(256) mi_kernel(const float* __restrict__ pred,
                                                 const float* __restrict__ targ,
                                                 const int* __restrict__ ip) {
    int row = blockIdx.x;
    const float* x = pred + (size_t)ip[0] * BROWS * NFFT + (size_t)row * NFFT;
    const float* y = targ + (size_t)row * NFFT;
    __shared__ float sred[32];
    __shared__ int hist[100];

    float xmn = 1e30f, xmx = -1e30f, ymn = 1e30f, ymx = -1e30f;
    for (int n = threadIdx.x; n < NFFT; n += blockDim.x) {
        float a = x[n], b = y[n];
        xmn = fminf(xmn, a); xmx = fmaxf(xmx, a);
        ymn = fminf(ymn, b); ymx = fmaxf(ymx, b);
    }
    xmn = blockMinAll(xmn, sred);
    xmx = blockMaxAll(xmx, sred);
    ymn = blockMinAll(ymn, sred);
    ymx = blockMaxAll(ymx, sred);

    float bwx = (xmx - xmn) / 10.0f;
    float bwy = (ymx - ymn) / 10.0f;

    for (int t = threadIdx.x; t < 100; t += blockDim.x) hist[t] = 0;
    __syncthreads();
    for (int n = threadIdx.x; n < NFFT; n += blockDim.x) {
        int ix = (int)((x[n] - xmn) / bwx);
        int iy = (int)((y[n] - ymn) / bwy);
        ix = min(max(ix, 0), 9);
        iy = min(max(iy, 0), 9);
        atomicAdd(&hist[ix * 10 + iy], 1);
    }
    __syncthreads();

    if (threadIdx.x == 0) {
        const double denom = (double)BROWS * (double)NFFT;
        const double eps = 1e-8;
        double hx[10], hy[10];
        for (int j = 0; j < 10; j++) { hx[j] = 0; hy[j] = 0; }
        for (int j = 0; j < 10; j++)
            for (int k = 0; k < 10; k++) {
                double h = (double)hist[j * 10 + k];
                hx[j] += h; hy[k] += h;
            }
        double mi = 0;
        for (int j = 0; j < 10; j++)
            for (int k = 0; k < 10; k++) {
                double pxy = (double)hist[j * 10 + k] / denom;
                double px = hx[j] / denom, py = hy[k] / denom;
                mi += pxy * log((pxy + eps) / (px * py + eps));
            }
        double hxe = 0, hye = 0;
        for (int j = 0; j < 10; j++) {
            double px = hx[j] / denom, py = hy[j] / denom;
            hxe -= px * log(px + eps);
            hye -= py * log(py + eps);
        }
        double nmi = mi / ((hxe + hye) * 0.5);
        atomicAdd(&g_acc[4], nmi);
    }
}

// ---------------------------------------------------------------- FFT (in shared mem)
__device__ void fft_inplace(float2* d) {
    int tid = threadIdx.x;
    // bit-reversal permutation
    for (int idx = tid; idx < NFFT; idx += FFT_THREADS) {
        int r = __brev((unsigned)idx) >> (32 - LOGN);
        if (r > idx) { float2 tmp = d[idx]; d[idx] = d[r]; d[r] = tmp; }
    }
    __syncthreads();
    for (int s = 1; s <= LOGN; s++) {
        int half = 1 << (s - 1);
        int step = NFFT >> s;
#pragma unroll 1
        for (int b = tid; b < NFFT / 2; b += FFT_THREADS) {
            int j = b & (half - 1);
            int k1 = ((b >> (s - 1)) << s) + j;
            int k2 = k1 + half;
            float2 w = g_tw[j * step];
            float2 a = d[k1];
            float2 t = cmul(d[k2], w);
            d[k1] = make_float2(a.x + t.x, a.y + t.y);
            d[k2] = make_float2(a.x - t.x, a.y - t.y);
        }
        __syncthreads();
    }
}

// ---------------------------------------------------------------- spectral terms
extern __shared__ float2 sdata[];

__global__ void __launch_bounds__(FFT_THREADS, 1)
spectral_kernel(const float* __restrict__ pred, const float* __restrict__ targ,
                const int* __restrict__ ip) {
    int row = blockIdx.x;
    const float* x = pred + (size_t)ip[0] * BROWS * NFFT + (size_t)row * NFFT;
    const float* y = targ + (size_t)row * NFFT;
    int tid = threadIdx.x;
    __shared__ double red[32];

    // ===== power spectrum: one complex FFT of z = x + i*t =====
    for (int n = tid; n < NFFT; n += FFT_THREADS)
        sdata[n] = make_float2(x[n], y[n]);
    __syncthreads();
    fft_inplace(sdata);
    double la = 0, lt = 0;
    for (int k = tid; k <= NFFT / 2; k += FFT_THREADS) {
        float2 Zk = sdata[k];
        float2 Zm = sdata[(NFFT - k) & (NFFT - 1)];
        float xr = 0.5f * (Zk.x + Zm.x), xi = 0.5f * (Zk.y - Zm.y);
        float yr = 0.5f * (Zk.y + Zm.y), yi = 0.5f * (Zm.x - Zk.x);
        float xp = xr * xr + xi * xi;
        float tp = yr * yr + yi * yi;
        la += fabsf(xp - tp);
        lt += tp;
    }
    double ba = blockReduceSumD(la, red);
    double bt = blockReduceSumD(lt, red);
    if (tid == 0) { atomicAdd(&g_acc[2], ba); atomicAdd(&g_acc[3], bt); }
    __syncthreads();

    // ===== phase correlation: windowed FFT, phase-only corr, inverse FFT, argmax =====
    const float invN = 1.0f / (float)NFFT;
    for (int n = tid; n < NFFT; n += FFT_THREADS) {
        float w = 0.5f * (1.0f - cospif(2.0f * (float)n * invN));
        sdata[n] = make_float2(x[n] * w, y[n] * w);
    }
    __syncthreads();
    fft_inplace(sdata);
    // build D = conj(full phase-correlation spectrum) in place; each pair (k, N-k)
    // is owned by exactly one thread -> no barrier needed inside the loop
    for (int k = tid; k <= NFFT / 2; k += FFT_THREADS) {
        int km = (NFFT - k) & (NFFT - 1);
        float2 Zk = sdata[k];
        float2 Zm = sdata[km];
        float xr = 0.5f * (Zk.x + Zm.x), xi = 0.5f * (Zk.y - Zm.y);
        float yr = 0.5f * (Zk.y + Zm.y), yi = 0.5f * (Zm.x - Zk.x);
        float cr = xr * yr + xi * yi;       // C = X * conj(T)
        float ci = xi * yr - xr * yi;
        float inv = rsqrtf(cr * cr + ci * ci);
        cr *= inv; ci *= inv;
        sdata[k] = make_float2(cr, -ci);    // D[k]   = conj(Chat)
        if (km != k) sdata[km] = make_float2(cr, ci);  // D[N-k] = Chat
    }
    __syncthreads();
    fft_inplace(sdata);   // irfft(Chat) ~ Re(result)/N ; argmax unaffected by 1/N
    float bv = -1e30f; int bi = 0;
    for (int n = tid; n < NFFT; n += FFT_THREADS) {
        float v = sdata[n].x;
        if (v > bv) { bv = v; bi = n; }     // strided scan keeps first-index within thread
    }
    __shared__ float sv[32];
    __shared__ int si[32];
    int lane = tid & 31, w = tid >> 5;
    for (int o = 16; o > 0; o >>= 1) {
        float ov = __shfl_down_sync(0xffffffffu, bv, o);
        int   oi = __shfl_down_sync(0xffffffffu, bi, o);
        if (ov > bv || (ov == bv && oi < bi)) { bv = ov; bi = oi; }
    }
    if (lane == 0) { sv[w] = bv; si[w] = bi; }
    __syncthreads();
    if (tid == 0) {
        int nw = FFT_THREADS >> 5;
        for (int iw = 1; iw < nw; iw++)
            if (sv[iw] > bv || (sv[iw] == bv && si[iw] < bi)) { bv = sv[iw]; bi = si[iw]; }
        atomicAdd(&g_acc[1], cospi(2.0 * (double)bi / (double)NFFT));
    }
}

// ---------------------------------------------------------------- finalize
__global__ void finalize_kernel(const int* __restrict__ ep, float* __restrict__ out) {
    double loss = g_acc[0] / (double)BROWS;          // neg pearson
    int epoch = ep[0];
    if (epoch >= 400) {
        loss += 1.0 - g_acc[1] / (double)BROWS;      // phase correlation
        loss += g_acc[2] / g_acc[3];                 // power spectrum
    }
    if (epoch >= 700) {
        loss += 1.0 - g_acc[4] / (double)BROWS;      // mutual information
    }
    out[0] = (float)loss;
}

// ---------------------------------------------------------------- launch
extern "C" void kernel_launch(void* const* d_in, const int* in_sizes, int n_in,
                              void* d_out, int out_size) {
    const float* pred = (const float*)d_in[0];   // [2, 512, 16384] f32
    const float* targ = (const float*)d_in[1];   // [512, 16384] f32
    const int* ip = (const int*)d_in[2];         // scalar i
    const int* ep = (const int*)d_in[3];         // scalar epoch
    float* out = (float*)d_out;

    cudaFuncSetAttribute(spectral_kernel,
                         cudaFuncAttributeMaxDynamicSharedMemorySize,
                         NFFT * (int)sizeof(float2));

    init_kernel<<<32, 256>>>();                                  // 8192 threads
    pearson_kernel<<<BROWS, 256>>>(pred, targ, ip);
    mi_kernel<<<BROWS, 256>>>(pred, targ, ip);
    spectral_kernel<<<BROWS, FFT_THREADS, NFFT * sizeof(float2)>>>(pred, targ, ip);
    finalize_kernel<<<1, 1>>>(ep, out);
}

// round 10
// speedup vs baseline: 3.6733x; 3.4808x over previous
#include <cuda_runtime.h>
#include <math.h>

#define NFFT 16384
#define BROWS 512
#define NT 1024

// accumulators: 0=sum(1-pear), 1=sum cos, 2=sum|xp-tp|, 3=sum tp, 4=sum nmi
__device__ double g_acc[5];
__device__ float2 g_tw[NFFT];   // W_N^t = exp(-2*pi*i*t/N)

// ---------------------------------------------------------------- init
__global__ void init_kernel() {
    int t = blockIdx.x * blockDim.x + threadIdx.x;
    if (t < 5) g_acc[t] = 0.0;
    if (t < NFFT) {
        double s, c;
        sincospi(-2.0 * (double)t / (double)NFFT, &s, &c);
        g_tw[t] = make_float2((float)c, (float)s);
    }
}

// ---------------------------------------------------------------- small helpers
__device__ __forceinline__ int PHYS(int a) { return a ^ ((a >> 4) & 15); }
// storage location of frequency k after the (16,16,16,4)-DIF forward FFT
__device__ __forceinline__ int LOCF(int k) {
    return ((k & 15) << 10) | (((k >> 4) & 15) << 6) | (((k >> 8) & 15) << 2) | (k >> 12);
}
__device__ __forceinline__ float2 cmul(float2 a, float2 b) {
    return make_float2(a.x * b.x - a.y * b.y, a.x * b.y + a.y * b.x);
}
__device__ __forceinline__ float2 cmulc(float2 a, float2 b) {  // a * conj(b)
    return make_float2(a.x * b.x + a.y * b.y, a.y * b.x - a.x * b.y);
}
__device__ __forceinline__ float2 mulnegi(float2 a) { return make_float2(a.y, -a.x); }
__device__ __forceinline__ float2 mulposi(float2 a) { return make_float2(-a.y, a.x); }

template<int INV>
__device__ __forceinline__ void dft4(float2& a, float2& b, float2& c, float2& d) {
    float2 e0 = make_float2(a.x + c.x, a.y + c.y);
    float2 e1 = make_float2(a.x - c.x, a.y - c.y);
    float2 o0 = make_float2(b.x + d.x, b.y + d.y);
    float2 o1 = make_float2(b.x - d.x, b.y - d.y);
    float2 r = INV ? mulposi(o1) : mulnegi(o1);
    a = make_float2(e0.x + o0.x, e0.y + o0.y);
    c = make_float2(e0.x - o0.x, e0.y - o0.y);
    b = make_float2(e1.x + r.x, e1.y + r.y);
    d = make_float2(e1.x - r.x, e1.y - r.y);
}
// multiply by W16^e = cr - i*si (fwd) / cr + i*si (inv)
template<int INV>
__device__ __forceinline__ float2 twm(float2 a, float cr, float si) {
    float s = INV ? si : -si;
    return make_float2(a.x * cr - a.y * s, a.x * s + a.y * cr);
}
// in-place 16-pt DFT; output freq r lands in slot ((r&3)<<2)|(r>>2)
template<int INV>
__device__ __forceinline__ void dft16(float2 v[16]) {
#pragma unroll
    for (int b = 0; b < 4; b++) dft4<INV>(v[b], v[b + 4], v[b + 8], v[b + 12]);
    const float C1 = 0.92387953251128675613f;
    const float S1 = 0.38268343236508977173f;
    const float R2 = 0.70710678118654752440f;
    v[5]  = twm<INV>(v[5],  C1,  S1);
    v[6]  = twm<INV>(v[6],  R2,  R2);
    v[7]  = twm<INV>(v[7],  S1,  C1);
    v[9]  = twm<INV>(v[9],  R2,  R2);
    v[10] = INV ? mulposi(v[10]) : mulnegi(v[10]);
    v[11] = twm<INV>(v[11], -R2,  R2);
    v[13] = twm<INV>(v[13],  S1,  C1);
    v[14] = twm<INV>(v[14], -R2,  R2);
    v[15] = twm<INV>(v[15], -C1, -S1);
#pragma unroll
    for (int c = 0; c < 4; c++) dft4<INV>(v[4 * c], v[4 * c + 1], v[4 * c + 2], v[4 * c + 3]);
}

// ---------------------------------------------------------------- merged FFT passes
// DIF forward (INV=0): v[m]=S[base+m*SUB]; y[r]=W_N^{j*TWSTEP*r}*DFT16(v)[r] -> S[base+r*SUB]
// DIT inverse (INV=1): u[r]=S[base+r*SUB]*conj(W); S[base+m*SUB]=IDFT16(u)[m]
template<int SUB, int TWSTEP, int INV>
__device__ __forceinline__ void pass16(float2* S) {
    int g = threadIdx.x;
    int j = g & (SUB - 1);
    int base = (g / SUB) * (16 * SUB) + j;
    int e = j * TWSTEP;
    float2 v[16];
    float2 w1 = g_tw[e], w4 = g_tw[4 * e], w8 = g_tw[8 * e], w12 = g_tw[12 * e];
    if (INV == 0) {
#pragma unroll
        for (int m = 0; m < 16; m++) v[m] = S[PHYS(base + m * SUB)];
        dft16<0>(v);
        S[PHYS(base)] = v[0];
        float2 wc = w1;
#pragma unroll
        for (int r = 1; r < 16; r++) {
            int slot = ((r & 3) << 2) | (r >> 2);
            if (r == 4) wc = w4; else if (r == 8) wc = w8; else if (r == 12) wc = w12;
            else if (r > 1) wc = cmul(wc, w1);
            S[PHYS(base + r * SUB)] = cmul(v[slot], wc);
        }
    } else {
        v[0] = S[PHYS(base)];
        float2 wc = w1;
#pragma unroll
        for (int r = 1; r < 16; r++) {
            if (r == 4) wc = w4; else if (r == 8) wc = w8; else if (r == 12) wc = w12;
            else if (r > 1) wc = cmul(wc, w1);
            v[r] = cmulc(S[PHYS(base + r * SUB)], wc);
        }
        dft16<1>(v);
#pragma unroll
        for (int m = 0; m < 16; m++)
            S[PHYS(base + m * SUB)] = v[((m & 3) << 2) | (m >> 2)];
    }
}

// final (fwd) / first (inv) radix-4 pass on contiguous blocks of 4, no twiddles
template<int INV>
__device__ __forceinline__ void pass4x(float2* S) {
#pragma unroll
    for (int q = 0; q < 4; q++) {
        int base = threadIdx.x * 16 + q * 4;
        float2 a = S[PHYS(base)], b = S[PHYS(base + 1)], c = S[PHYS(base + 2)], d = S[PHYS(base + 3)];
        dft4<INV>(a, b, c, d);
        S[PHYS(base)] = a; S[PHYS(base + 1)] = b; S[PHYS(base + 2)] = c; S[PHYS(base + 3)] = d;
    }
}

__device__ __forceinline__ void fwd_fft(float2* S) {
    pass16<1024, 1, 0>(S);  __syncthreads();
    pass16<64, 16, 0>(S);   __syncthreads();
    pass16<4, 256, 0>(S);   __syncthreads();
    pass4x<0>(S);           __syncthreads();
}
__device__ __forceinline__ void inv_fft(float2* S) {
    pass4x<1>(S);           __syncthreads();
    pass16<4, 256, 1>(S);   __syncthreads();
    pass16<64, 16, 1>(S);   __syncthreads();
    pass16<1024, 1, 1>(S);  __syncthreads();
}

// ---------------------------------------------------------------- reductions
__device__ __forceinline__ double blockReduceSumD(double v, double* s) {
    for (int o = 16; o > 0; o >>= 1) v += __shfl_down_sync(0xffffffffu, v, o);
    int lane = threadIdx.x & 31, w = threadIdx.x >> 5;
    __syncthreads();
    if (lane == 0) s[w] = v;
    __syncthreads();
    if (threadIdx.x == 0) {
        int nw = blockDim.x >> 5;
        double r = s[0];
        for (int i = 1; i < nw; i++) r += s[i];
        v = r;
    }
    return v;  // valid on thread 0
}
__device__ __forceinline__ float blockMinAll(float v, float* s) {
    for (int o = 16; o > 0; o >>= 1) v = fminf(v, __shfl_down_sync(0xffffffffu, v, o));
    int lane = threadIdx.x & 31, w = threadIdx.x >> 5;
    __syncthreads();
    if (lane == 0) s[w] = v;
    __syncthreads();
    if (threadIdx.x == 0) {
        int nw = blockDim.x >> 5;
        float r = s[0];
        for (int i = 1; i < nw; i++) r = fminf(r, s[i]);
        s[0] = r;
    }
    __syncthreads();
    float r = s[0];
    __syncthreads();
    return r;
}
__device__ __forceinline__ float blockMaxAll(float v, float* s) {
    for (int o = 16; o > 0; o >>= 1) v = fmaxf(v, __shfl_down_sync(0xffffffffu, v, o));
    int lane = threadIdx.x & 31, w = threadIdx.x >> 5;
    __syncthreads();
    if (lane == 0) s[w] = v;
    __syncthreads();
    if (threadIdx.x == 0) {
        int nw = blockDim.x >> 5;
        float r = s[0];
        for (int i = 1; i < nw; i++) r = fmaxf(r, s[i]);
        s[0] = r;
    }
    __syncthreads();
    float r = s[0];
    __syncthreads();
    return r;
}

// ---------------------------------------------------------------- fused kernel
extern __shared__ float2 sdata[];

__global__ void __launch_bounds__(NT, 1)
fused_kernel(const float* __restrict__ pred, const float* __restrict__ targ,
             const int* __restrict__ ip) {
    __shared__ double red[32];
    __shared__ float sred[32];
    __shared__ int hist[100];
    __shared__ float sv[32];
    __shared__ int si[32];

    int row = blockIdx.x;
    const float* xg = pred + (size_t)ip[0] * BROWS * NFFT + (size_t)row * NFFT;
    const float* yg = targ + (size_t)row * NFFT;
    int tid = threadIdx.x;

    // ===== Phase A: load once -> regs; pearson partials, min/max; z=(x,y) -> smem =====
    float xv[16], yv[16];
    float fsx = 0, fsy = 0, fsxy = 0, fsx2 = 0, fsy2 = 0;
    float xmn = 1e30f, xmx = -1e30f, ymn = 1e30f, ymx = -1e30f;
#pragma unroll
    for (int k = 0; k < 16; k++) {
        int n = tid + k * NT;
        float a = xg[n], b = yg[n];
        xv[k] = a; yv[k] = b;
        fsx += a; fsy += b; fsxy += a * b; fsx2 += a * a; fsy2 += b * b;
        xmn = fminf(xmn, a); xmx = fmaxf(xmx, a);
        ymn = fminf(ymn, b); ymx = fmaxf(ymx, b);
        sdata[PHYS(n)] = make_float2(a, b);
    }
    if (tid < 100) hist[tid] = 0;

    // pearson
    double rsx  = blockReduceSumD(fsx, red);
    double rsy  = blockReduceSumD(fsy, red);
    double rsxy = blockReduceSumD(fsxy, red);
    double rsx2 = blockReduceSumD(fsx2, red);
    double rsy2 = blockReduceSumD(fsy2, red);
    if (tid == 0) {
        double Nd = (double)NFFT;
        double num = Nd * rsxy - rsx * rsy;
        double den = sqrt((Nd * rsx2 - rsx * rsx) * (Nd * rsy2 - rsy * rsy));
        atomicAdd(&g_acc[0], 1.0 - num / den);
    }

    // ===== Phase B: MI histogram from registers + parallel NMI tail =====
    xmn = blockMinAll(xmn, sred);
    xmx = blockMaxAll(xmx, sred);
    ymn = blockMinAll(ymn, sred);
    ymx = blockMaxAll(ymx, sred);
    float bwx = (xmx - xmn) / 10.0f;
    float bwy = (ymx - ymn) / 10.0f;
#pragma unroll
    for (int k = 0; k < 16; k++) {
        int ix = min(max((int)((xv[k] - xmn) / bwx), 0), 9);
        int iy = min(max((int)((yv[k] - ymn) / bwy), 0), 9);
        atomicAdd(&hist[ix * 10 + iy], 1);
    }
    __syncthreads();
    double miT = 0.0, entT = 0.0;
    if (tid < 100) {
        int j = tid / 10, kk = tid % 10;
        const double denom = (double)BROWS * (double)NFFT;
        const double eps = 1e-8;
        double hx = 0, hy = 0;
        for (int c = 0; c < 10; c++) { hx += hist[j * 10 + c]; hy += hist[c * 10 + kk]; }
        double pxy = (double)hist[tid] / denom;
        double px = hx / denom, py = hy / denom;
        miT = pxy * log((pxy + eps) / (px * py + eps));
        if (kk == 0) entT -= px * log(px + eps);   // hxe_j
        if (j == 0)  entT -= py * log(py + eps);   // hye_kk
    }
    double miS  = blockReduceSumD(miT, red);
    double entS = blockReduceSumD(entT, red);
    if (tid == 0) atomicAdd(&g_acc[4], miS / (entS * 0.5));
    __syncthreads();

    // ===== Phase C/D: forward FFT of z=x+iy; power spectrum =====
    fwd_fft(sdata);
    float la = 0, lt = 0;
    for (int k = tid; k <= NFFT / 2; k += NT) {
        int km = (NFFT - k) & (NFFT - 1);
        float2 Zk = sdata[PHYS(LOCF(k))];
        float2 Zm = sdata[PHYS(LOCF(km))];
        float xr = 0.5f * (Zk.x + Zm.x), xi = 0.5f * (Zk.y - Zm.y);
        float yr = 0.5f * (Zk.y + Zm.y), yi = 0.5f * (Zm.x - Zk.x);
        float xp = xr * xr + xi * xi;
        float tp = yr * yr + yi * yi;
        la += fabsf(xp - tp);
        lt += tp;
    }
    double ba = blockReduceSumD((double)la, red);
    double bt = blockReduceSumD((double)lt, red);
    if (tid == 0) { atomicAdd(&g_acc[2], ba); atomicAdd(&g_acc[3], bt); }
    __syncthreads();

    // ===== Phase E/F/G: windowed FFT, phase-only correlation, inverse FFT =====
    const float i2N = 2.0f / (float)NFFT;
#pragma unroll
    for (int k = 0; k < 16; k++) {
        int n = tid + k * NT;
        float w = 0.5f * (1.0f - cospif((float)n * i2N));
        sdata[PHYS(n)] = make_float2(xv[k] * w, yv[k] * w);
    }
    __syncthreads();
    fwd_fft(sdata);
    for (int k = tid; k <= NFFT / 2; k += NT) {
        int km = (NFFT - k) & (NFFT - 1);
        int pk = PHYS(LOCF(k)), pm = PHYS(LOCF(km));
        float2 Zk = sdata[pk];
        float2 Zm = sdata[pm];
        float xr = 0.5f * (Zk.x + Zm.x), xi = 0.5f * (Zk.y - Zm.y);
        float yr = 0.5f * (Zk.y + Zm.y), yi = 0.5f * (Zm.x - Zk.x);
        float cr = xr * yr + xi * yi;      // C = X * conj(T)
        float ci = xi * yr - xr * yi;
        float inv = rsqrtf(cr * cr + ci * ci);
        cr *= inv; ci *= inv;
        sdata[pk] = make_float2(cr, ci);                 // Chat[k]
        if (pm != pk) sdata[pm] = make_float2(cr, -ci);  // Chat[N-k] = conj
    }
    __syncthreads();
    inv_fft(sdata);   // true inverse -> natural order; scale N* irrelevant for argmax

    // ===== Phase H: argmax of real part =====
    float bv = -1e30f; int bi = 0;
#pragma unroll
    for (int k = 0; k < 16; k++) {
        int n = tid + k * NT;
        float v = sdata[PHYS(n)].x;
        if (v > bv) { bv = v; bi = n; }
    }
    int lane = tid & 31, w = tid >> 5;
    for (int o = 16; o > 0; o >>= 1) {
        float ov = __shfl_down_sync(0xffffffffu, bv, o);
        int   oi = __shfl_down_sync(0xffffffffu, bi, o);
        if (ov > bv || (ov == bv && oi < bi)) { bv = ov; bi = oi; }
    }
    if (lane == 0) { sv[w] = bv; si[w] = bi; }
    __syncthreads();
    if (tid == 0) {
        for (int iw = 1; iw < 32; iw++)
            if (sv[iw] > bv || (sv[iw] == bv && si[iw] < bi)) { bv = sv[iw]; bi = si[iw]; }
        atomicAdd(&g_acc[1], cospi(2.0 * (double)bi / (double)NFFT));
    }
}

// ---------------------------------------------------------------- finalize
__global__ void finalize_kernel(const int* __restrict__ ep, float* __restrict__ out) {
    double loss = g_acc[0] / (double)BROWS;          // neg pearson
    int epoch = ep[0];
    if (epoch >= 400) {
        loss += 1.0 - g_acc[1] / (double)BROWS;      // phase correlation
        loss += g_acc[2] / g_acc[3];                 // power spectrum
    }
    if (epoch >= 700) {
        loss += 1.0 - g_acc[4] / (double)BROWS;      // mutual information
    }
    out[0] = (float)loss;
}

// ---------------------------------------------------------------- launch
extern "C" void kernel_launch(void* const* d_in, const int* in_sizes, int n_in,
                              void* d_out, int out_size) {
    const float* pred = (const float*)d_in[0];   // [2, 512, 16384] f32
    const float* targ = (const float*)d_in[1];   // [512, 16384] f32
    const int* ip = (const int*)d_in[2];         // scalar i
    const int* ep = (const int*)d_in[3];         // scalar epoch
    float* out = (float*)d_out;

    cudaFuncSetAttribute(fused_kernel,
                         cudaFuncAttributeMaxDynamicSharedMemorySize,
                         NFFT * (int)sizeof(float2));

    init_kernel<<<64, 256>>>();
    fused_kernel<<<BROWS, NT, NFFT * sizeof(float2)>>>(pred, targ, ip);
    finalize_kernel<<<1, 1>>>(ep, out);
}

// round 13
// speedup vs baseline: 4.0290x; 1.0968x over previous
#include <cuda_runtime.h>
#include <math.h>

#define NFFT 16384
#define BROWS 512
#define NT 512
#define EPT 32            // elements per thread in pointwise phases

// accumulators: 0=sum(1-pear), 1=sum cos, 2=sum|xp-tp|, 3=sum tp, 4=sum nmi
__device__ double g_acc[5];
__device__ float2 g_tw[NFFT];   // W_N^t = exp(-2*pi*i*t/N)

// ---------------------------------------------------------------- init
__global__ void init_kernel() {
    int t = blockIdx.x * blockDim.x + threadIdx.x;
    if (t < 5) g_acc[t] = 0.0;
    if (t < NFFT) {
        double s, c;
        sincospi(-2.0 * (double)t / (double)NFFT, &s, &c);
        g_tw[t] = make_float2((float)c, (float)s);
    }
}

// ---------------------------------------------------------------- small helpers
__device__ __forceinline__ int PHYS(int a) { return a ^ ((a >> 4) & 15); }
// storage location of frequency k after the (16,16,16,4)-DIF forward FFT
__device__ __forceinline__ int LOCF(int k) {
    return ((k & 15) << 10) | (((k >> 4) & 15) << 6) | (((k >> 8) & 15) << 2) | (k >> 12);
}
__device__ __forceinline__ float2 cmul(float2 a, float2 b) {
    return make_float2(a.x * b.x - a.y * b.y, a.x * b.y + a.y * b.x);
}
__device__ __forceinline__ float2 cmulc(float2 a, float2 b) {  // a * conj(b)
    return make_float2(a.x * b.x + a.y * b.y, a.y * b.x - a.x * b.y);
}
__device__ __forceinline__ float2 mulnegi(float2 a) { return make_float2(a.y, -a.x); }
__device__ __forceinline__ float2 mulposi(float2 a) { return make_float2(-a.y, a.x); }

template<int INV>
__device__ __forceinline__ void dft4(float2& a, float2& b, float2& c, float2& d) {
    float2 e0 = make_float2(a.x + c.x, a.y + c.y);
    float2 e1 = make_float2(a.x - c.x, a.y - c.y);
    float2 o0 = make_float2(b.x + d.x, b.y + d.y);
    float2 o1 = make_float2(b.x - d.x, b.y - d.y);
    float2 r = INV ? mulposi(o1) : mulnegi(o1);
    a = make_float2(e0.x + o0.x, e0.y + o0.y);
    c = make_float2(e0.x - o0.x, e0.y - o0.y);
    b = make_float2(e1.x + r.x, e1.y + r.y);
    d = make_float2(e1.x - r.x, e1.y - r.y);
}
// multiply by W16^e = cr - i*si (fwd) / cr + i*si (inv)
template<int INV>
__device__ __forceinline__ float2 twm(float2 a, float cr, float si) {
    float s = INV ? si : -si;
    return make_float2(a.x * cr - a.y * s, a.x * s + a.y * cr);
}
// in-place 16-pt DFT; output freq r lands in slot ((r&3)<<2)|(r>>2)
template<int INV>
__device__ __forceinline__ void dft16(float2 v[16]) {
#pragma unroll
    for (int b = 0; b < 4; b++) dft4<INV>(v[b], v[b + 4], v[b + 8], v[b + 12]);
    const float C1 = 0.92387953251128675613f;
    const float S1 = 0.38268343236508977173f;
    const float R2 = 0.70710678118654752440f;
    v[5]  = twm<INV>(v[5],  C1,  S1);
    v[6]  = twm<INV>(v[6],  R2,  R2);
    v[7]  = twm<INV>(v[7],  S1,  C1);
    v[9]  = twm<INV>(v[9],  R2,  R2);
    v[10] = INV ? mulposi(v[10]) : mulnegi(v[10]);
    v[11] = twm<INV>(v[11], -R2,  R2);
    v[13] = twm<INV>(v[13],  S1,  C1);
    v[14] = twm<INV>(v[14], -R2,  R2);
    v[15] = twm<INV>(v[15], -C1, -S1);
#pragma unroll
    for (int c = 0; c < 4; c++) dft4<INV>(v[4 * c], v[4 * c + 1], v[4 * c + 2], v[4 * c + 3]);
}

// ---------------------------------------------------------------- merged FFT passes
// Each thread processes 2 butterflies (g = tid and tid+NT), sequentially, so the
// 32-register butterfly working set is never live twice.
// DIF forward (INV=0): v[m]=S[base+m*SUB]; y[r]=W_N^{j*TWSTEP*r}*DFT16(v)[r] -> S[base+r*SUB]
// DIT inverse (INV=1): u[r]=S[base+r*SUB]*conj(W); S[base+m*SUB]=IDFT16(u)[m]
template<int SUB, int TWSTEP, int INV>
__device__ __forceinline__ void pass16(float2* S) {
#pragma unroll
    for (int h = 0; h < 2; h++) {
        int g = threadIdx.x + h * NT;          // butterfly index in [0, 1024)
        int j = g & (SUB - 1);
        int base = (g / SUB) * (16 * SUB) + j;
        int e = j * TWSTEP;
        float2 v[16];
        float2 w1 = g_tw[e], w4 = g_tw[4 * e], w8 = g_tw[8 * e], w12 = g_tw[12 * e];
        if (INV == 0) {
#pragma unroll
            for (int m = 0; m < 16; m++) v[m] = S[PHYS(base + m * SUB)];
            dft16<0>(v);
            S[PHYS(base)] = v[0];
            float2 wc = w1;
#pragma unroll
            for (int r = 1; r < 16; r++) {
                int slot = ((r & 3) << 2) | (r >> 2);
                if (r == 4) wc = w4; else if (r == 8) wc = w8; else if (r == 12) wc = w12;
                else if (r > 1) wc = cmul(wc, w1);
                S[PHYS(base + r * SUB)] = cmul(v[slot], wc);
            }
        } else {
            v[0] = S[PHYS(base)];
            float2 wc = w1;
#pragma unroll
            for (int r = 1; r < 16; r++) {
                if (r == 4) wc = w4; else if (r == 8) wc = w8; else if (r == 12) wc = w12;
                else if (r > 1) wc = cmul(wc, w1);
                v[r] = cmulc(S[PHYS(base + r * SUB)], wc);
            }
            dft16<1>(v);
#pragma unroll
            for (int m = 0; m < 16; m++)
                S[PHYS(base + m * SUB)] = v[((m & 3) << 2) | (m >> 2)];
        }
    }
}

// final (fwd) / first (inv) radix-4 pass on contiguous blocks of 4, no twiddles.
// quad index b = tid + q*NT keeps the 16-lane LDS phases conflict-free under PHYS.
template<int INV>
__device__ __forceinline__ void pass4x(float2* S) {
#pragma unroll
    for (int q = 0; q < 8; q++) {
        int b = threadIdx.x + q * NT;          // quad index in [0, 4096)
        int base = b * 4;
        float2 a = S[PHYS(base)], bb = S[PHYS(base + 1)], c = S[PHYS(base + 2)], d = S[PHYS(base + 3)];
        dft4<INV>(a, bb, c, d);
        S[PHYS(base)] = a; S[PHYS(base + 1)] = bb; S[PHYS(base + 2)] = c; S[PHYS(base + 3)] = d;
    }
}

__device__ __forceinline__ void fwd_fft(float2* S) {
    pass16<1024, 1, 0>(S);  __syncthreads();
    pass16<64, 16, 0>(S);   __syncthreads();
    pass16<4, 256, 0>(S);   __syncthreads();
    pass4x<0>(S);           __syncthreads();
}
__device__ __forceinline__ void inv_fft(float2* S) {
    pass4x<1>(S);           __syncthreads();
    pass16<4, 256, 1>(S);   __syncthreads();
    pass16<64, 16, 1>(S);   __syncthreads();
    pass16<1024, 1, 1>(S);  __syncthreads();
}

// ---------------------------------------------------------------- reductions
__device__ __forceinline__ double blockReduceSumD(double v, double* s) {
    for (int o = 16; o > 0; o >>= 1) v += __shfl_down_sync(0xffffffffu, v, o);
    int lane = threadIdx.x & 31, w = threadIdx.x >> 5;
    __syncthreads();
    if (lane == 0) s[w] = v;
    __syncthreads();
    if (threadIdx.x == 0) {
        int nw = blockDim.x >> 5;
        double r = s[0];
        for (int i = 1; i < nw; i++) r += s[i];
        v = r;
    }
    return v;  // valid on thread 0
}
__device__ __forceinline__ float blockMinAll(float v, float* s) {
    for (int o = 16; o > 0; o >>= 1) v = fminf(v, __shfl_down_sync(0xffffffffu, v, o));
    int lane = threadIdx.x & 31, w = threadIdx.x >> 5;
    __syncthreads();
    if (lane == 0) s[w] = v;
    __syncthreads();
    if (threadIdx.x == 0) {
        int nw = blockDim.x >> 5;
        float r = s[0];
        for (int i = 1; i < nw; i++) r = fminf(r, s[i]);
        s[0] = r;
    }
    __syncthreads();
    float r = s[0];
    __syncthreads();
    return r;
}
__device__ __forceinline__ float blockMaxAll(float v, float* s) {
    for (int o = 16; o > 0; o >>= 1) v = fmaxf(v, __shfl_down_sync(0xffffffffu, v, o));
    int lane = threadIdx.x & 31, w = threadIdx.x >> 5;
    __syncthreads();
    if (lane == 0) s[w] = v;
    __syncthreads();
    if (threadIdx.x == 0) {
        int nw = blockDim.x >> 5;
        float r = s[0];
        for (int i = 1; i < nw; i++) r = fmaxf(r, s[i]);
        s[0] = r;
    }
    __syncthreads();
    float r = s[0];
    __syncthreads();
    return r;
}

// ---------------------------------------------------------------- fused kernel
extern __shared__ float2 sdata[];

__global__ void __launch_bounds__(NT, 1)
fused_kernel(const float* __restrict__ pred, const float* __restrict__ targ,
             const int* __restrict__ ip) {
    __shared__ double red[32];
    __shared__ float sred[32];
    __shared__ int hist[100];
    __shared__ float sv[NT / 32];
    __shared__ int si[NT / 32];

    int row = blockIdx.x;
    const float* xg = pred + (size_t)ip[0] * BROWS * NFFT + (size_t)row * NFFT;
    const float* yg = targ + (size_t)row * NFFT;
    int tid = threadIdx.x;

    // ===== Phase A: load; pearson partials + min/max; z=(x,y) -> smem =====
    float fsx = 0, fsy = 0, fsxy = 0, fsx2 = 0, fsy2 = 0;
    float xmn = 1e30f, xmx = -1e30f, ymn = 1e30f, ymx = -1e30f;
#pragma unroll
    for (int k = 0; k < EPT; k++) {
        int n = tid + k * NT;
        float a = xg[n], b = yg[n];
        fsx += a; fsy += b; fsxy += a * b; fsx2 += a * a; fsy2 += b * b;
        xmn = fminf(xmn, a); xmx = fmaxf(xmx, a);
        ymn = fminf(ymn, b); ymx = fmaxf(ymx, b);
        sdata[PHYS(n)] = make_float2(a, b);
    }
    if (tid < 100) hist[tid] = 0;

    // pearson
    double rsx  = blockReduceSumD(fsx, red);
    double rsy  = blockReduceSumD(fsy, red);
    double rsxy = blockReduceSumD(fsxy, red);
    double rsx2 = blockReduceSumD(fsx2, red);
    double rsy2 = blockReduceSumD(fsy2, red);
    if (tid == 0) {
        double Nd = (double)NFFT;
        double num = Nd * rsxy - rsx * rsy;
        double den = sqrt((Nd * rsx2 - rsx * rsx) * (Nd * rsy2 - rsy * rsy));
        atomicAdd(&g_acc[0], 1.0 - num / den);
    }

    // ===== Phase B: MI histogram (x,y reloaded from L2-hot global) + NMI tail =====
    xmn = blockMinAll(xmn, sred);
    xmx = blockMaxAll(xmx, sred);
    ymn = blockMinAll(ymn, sred);
    ymx = blockMaxAll(ymx, sred);
    float bwx = (xmx - xmn) / 10.0f;
    float bwy = (ymx - ymn) / 10.0f;
#pragma unroll 4
    for (int k = 0; k < EPT; k++) {
        int n = tid + k * NT;
        int ix = min(max((int)((xg[n] - xmn) / bwx), 0), 9);
        int iy = min(max((int)((yg[n] - ymn) / bwy), 0), 9);
        atomicAdd(&hist[ix * 10 + iy], 1);
    }
    __syncthreads();
    double miT = 0.0, entT = 0.0;
    if (tid < 100) {
        int j = tid / 10, kk = tid % 10;
        const double denom = (double)BROWS * (double)NFFT;
        const double eps = 1e-8;
        double hx = 0, hy = 0;
        for (int c = 0; c < 10; c++) { hx += hist[j * 10 + c]; hy += hist[c * 10 + kk]; }
        double pxy = (double)hist[tid] / denom;
        double px = hx / denom, py = hy / denom;
        miT = pxy * log((pxy + eps) / (px * py + eps));
        if (kk == 0) entT -= px * log(px + eps);   // hxe_j
        if (j == 0)  entT -= py * log(py + eps);   // hye_kk
    }
    double miS  = blockReduceSumD(miT, red);
    double entS = blockReduceSumD(entT, red);
    if (tid == 0) atomicAdd(&g_acc[4], miS / (entS * 0.5));
    __syncthreads();

    // ===== Phase C/D: forward FFT of z=x+iy; power spectrum =====
    fwd_fft(sdata);
    float la = 0, lt = 0;
    for (int k = tid; k <= NFFT / 2; k += NT) {
        int km = (NFFT - k) & (NFFT - 1);
        float2 Zk = sdata[PHYS(LOCF(k))];
        float2 Zm = sdata[PHYS(LOCF(km))];
        float xr = 0.5f * (Zk.x + Zm.x), xi = 0.5f * (Zk.y - Zm.y);
        float yr = 0.5f * (Zk.y + Zm.y), yi = 0.5f * (Zm.x - Zk.x);
        float xp = xr * xr + xi * xi;
        float tp = yr * yr + yi * yi;
        la += fabsf(xp - tp);
        lt += tp;
    }
    double ba = blockReduceSumD((double)la, red);
    double bt = blockReduceSumD((double)lt, red);
    if (tid == 0) { atomicAdd(&g_acc[2], ba); atomicAdd(&g_acc[3], bt); }
    __syncthreads();

    // ===== Phase E/F/G: windowed FFT, phase-only correlation, inverse FFT =====
    const float i2N = 2.0f / (float)NFFT;
#pragma unroll
    for (int k = 0; k < EPT; k++) {
        int n = tid + k * NT;
        float w = 0.5f * (1.0f - cospif((float)n * i2N));
        sdata[PHYS(n)] = make_float2(xg[n] * w, yg[n] * w);
    }
    __syncthreads();
    fwd_fft(sdata);
    for (int k = tid; k <= NFFT / 2; k += NT) {
        int km = (NFFT - k) & (NFFT - 1);
        int pk = PHYS(LOCF(k)), pm = PHYS(LOCF(km));
        float2 Zk = sdata[pk];
        float2 Zm = sdata[pm];
        float xr = 0.5f * (Zk.x + Zm.x), xi = 0.5f * (Zk.y - Zm.y);
        float yr = 0.5f * (Zk.y + Zm.y), yi = 0.5f * (Zm.x - Zk.x);
        float cr = xr * yr + xi * yi;      // C = X * conj(T)
        float ci = xi * yr - xr * yi;
        float inv = rsqrtf(cr * cr + ci * ci);
        cr *= inv; ci *= inv;
        sdata[pk] = make_float2(cr, ci);                 // Chat[k]
        if (pm != pk) sdata[pm] = make_float2(cr, -ci);  // Chat[N-k] = conj
    }
    __syncthreads();
    inv_fft(sdata);   // true inverse -> natural order; 1/N scale irrelevant for argmax

    // ===== Phase H: argmax of real part =====
    float bv = -1e30f; int bi = 0;
#pragma unroll
    for (int k = 0; k < EPT; k++) {
        int n = tid + k * NT;
        float v = sdata[PHYS(n)].x;
        if (v > bv) { bv = v; bi = n; }
    }
    int lane = tid & 31, w = tid >> 5;
    for (int o = 16; o > 0; o >>= 1) {
        float ov = __shfl_down_sync(0xffffffffu, bv, o);
        int   oi = __shfl_down_sync(0xffffffffu, bi, o);
        if (ov > bv || (ov == bv && oi < bi)) { bv = ov; bi = oi; }
    }
    if (lane == 0) { sv[w] = bv; si[w] = bi; }
    __syncthreads();
    if (tid == 0) {
        for (int iw = 1; iw < NT / 32; iw++)
            if (sv[iw] > bv || (sv[iw] == bv && si[iw] < bi)) { bv = sv[iw]; bi = si[iw]; }
        atomicAdd(&g_acc[1], cospi(2.0 * (double)bi / (double)NFFT));
    }
}

// ---------------------------------------------------------------- finalize
__global__ void finalize_kernel(const int* __restrict__ ep, float* __restrict__ out) {
    double loss = g_acc[0] / (double)BROWS;          // neg pearson
    int epoch = ep[0];
    if (epoch >= 400) {
        loss += 1.0 - g_acc[1] / (double)BROWS;      // phase correlation
        loss += g_acc[2] / g_acc[3];                 // power spectrum
    }
    if (epoch >= 700) {
        loss += 1.0 - g_acc[4] / (double)BROWS;      // mutual information
    }
    out[0] = (float)loss;
}

// ---------------------------------------------------------------- launch
extern "C" void kernel_launch(void* const* d_in, const int* in_sizes, int n_in,
                              void* d_out, int out_size) {
    const float* pred = (const float*)d_in[0];   // [2, 512, 16384] f32
    const float* targ = (const float*)d_in[1];   // [512, 16384] f32
    const int* ip = (const int*)d_in[2];         // scalar i
    const int* ep = (const int*)d_in[3];         // scalar epoch
    float* out = (float*)d_out;

    cudaFuncSetAttribute(fused_kernel,
                         cudaFuncAttributeMaxDynamicSharedMemorySize,
                         NFFT * (int)sizeof(float2));

    init_kernel<<<64, 256>>>();
    fused_kernel<<<BROWS, NT, NFFT * sizeof(float2)>>>(pred, targ, ip);
    finalize_kernel<<<1, 1>>>(ep, out);
}

// round 15
// speedup vs baseline: 6.3974x; 1.5879x over previous
#include <cuda_runtime.h>
#include <math.h>

#define NFFT 16384
#define BROWS 512
#define NT 512
#define EPT 32            // elements per thread in pointwise phases

// accumulators: 0=sum(1-pear), 1=sum cos, 2=sum|xp-tp|, 3=sum tp, 4=sum nmi
__device__ double g_acc[5];
__device__ float2 g_tw[NFFT];   // W_N^t = exp(-2*pi*i*t/N)

// ---------------------------------------------------------------- init
__global__ void init_kernel() {
    int t = blockIdx.x * blockDim.x + threadIdx.x;
    if (t < 5) g_acc[t] = 0.0;
    if (t < NFFT) {
        double s, c;
        sincospi(-2.0 * (double)t / (double)NFFT, &s, &c);
        g_tw[t] = make_float2((float)c, (float)s);
    }
}

// ---------------------------------------------------------------- small helpers
__device__ __forceinline__ int PHYS(int a) { return a ^ ((a >> 4) & 15); }
// storage location of frequency k after the (16,16,16,4)-DIF forward FFT
__device__ __forceinline__ int LOCF(int k) {
    return ((k & 15) << 10) | (((k >> 4) & 15) << 6) | (((k >> 8) & 15) << 2) | (k >> 12);
}
__device__ __forceinline__ float2 cmul(float2 a, float2 b) {
    return make_float2(a.x * b.x - a.y * b.y, a.x * b.y + a.y * b.x);
}
__device__ __forceinline__ float2 cmulc(float2 a, float2 b) {  // a * conj(b)
    return make_float2(a.x * b.x + a.y * b.y, a.y * b.x - a.x * b.y);
}
__device__ __forceinline__ float2 mulnegi(float2 a) { return make_float2(a.y, -a.x); }
__device__ __forceinline__ float2 mulposi(float2 a) { return make_float2(-a.y, a.x); }

template<int INV>
__device__ __forceinline__ void dft4(float2& a, float2& b, float2& c, float2& d) {
    float2 e0 = make_float2(a.x + c.x, a.y + c.y);
    float2 e1 = make_float2(a.x - c.x, a.y - c.y);
    float2 o0 = make_float2(b.x + d.x, b.y + d.y);
    float2 o1 = make_float2(b.x - d.x, b.y - d.y);
    float2 r = INV ? mulposi(o1) : mulnegi(o1);
    a = make_float2(e0.x + o0.x, e0.y + o0.y);
    c = make_float2(e0.x - o0.x, e0.y - o0.y);
    b = make_float2(e1.x + r.x, e1.y + r.y);
    d = make_float2(e1.x - r.x, e1.y - r.y);
}
// multiply by W16^e = cr - i*si (fwd) / cr + i*si (inv)
template<int INV>
__device__ __forceinline__ float2 twm(float2 a, float cr, float si) {
    float s = INV ? si : -si;
    return make_float2(a.x * cr - a.y * s, a.x * s + a.y * cr);
}
// in-place 16-pt DFT; output freq r lands in slot ((r&3)<<2)|(r>>2)
template<int INV>
__device__ __forceinline__ void dft16(float2 v[16]) {
#pragma unroll
    for (int b = 0; b < 4; b++) dft4<INV>(v[b], v[b + 4], v[b + 8], v[b + 12]);
    const float C1 = 0.92387953251128675613f;
    const float S1 = 0.38268343236508977173f;
    const float R2 = 0.70710678118654752440f;
    v[5]  = twm<INV>(v[5],  C1,  S1);
    v[6]  = twm<INV>(v[6],  R2,  R2);
    v[7]  = twm<INV>(v[7],  S1,  C1);
    v[9]  = twm<INV>(v[9],  R2,  R2);
    v[10] = INV ? mulposi(v[10]) : mulnegi(v[10]);
    v[11] = twm<INV>(v[11], -R2,  R2);
    v[13] = twm<INV>(v[13],  S1,  C1);
    v[14] = twm<INV>(v[14], -R2,  R2);
    v[15] = twm<INV>(v[15], -C1, -S1);
#pragma unroll
    for (int c = 0; c < 4; c++) dft4<INV>(v[4 * c], v[4 * c + 1], v[4 * c + 2], v[4 * c + 3]);
}

// ---------------------------------------------------------------- merged FFT passes
// Each thread processes 2 butterflies (g = tid and tid+NT), sequentially.
template<int SUB, int TWSTEP, int INV>
__device__ __forceinline__ void pass16(float2* S) {
#pragma unroll
    for (int h = 0; h < 2; h++) {
        int g = threadIdx.x + h * NT;          // butterfly index in [0, 1024)
        int j = g & (SUB - 1);
        int base = (g / SUB) * (16 * SUB) + j;
        int e = j * TWSTEP;
        float2 v[16];
        float2 w1 = g_tw[e], w4 = g_tw[4 * e], w8 = g_tw[8 * e], w12 = g_tw[12 * e];
        if (INV == 0) {
#pragma unroll
            for (int m = 0; m < 16; m++) v[m] = S[PHYS(base + m * SUB)];
            dft16<0>(v);
            S[PHYS(base)] = v[0];
            float2 wc = w1;
#pragma unroll
            for (int r = 1; r < 16; r++) {
                int slot = ((r & 3) << 2) | (r >> 2);
                if (r == 4) wc = w4; else if (r == 8) wc = w8; else if (r == 12) wc = w12;
                else if (r > 1) wc = cmul(wc, w1);
                S[PHYS(base + r * SUB)] = cmul(v[slot], wc);
            }
        } else {
            v[0] = S[PHYS(base)];
            float2 wc = w1;
#pragma unroll
            for (int r = 1; r < 16; r++) {
                if (r == 4) wc = w4; else if (r == 8) wc = w8; else if (r == 12) wc = w12;
                else if (r > 1) wc = cmul(wc, w1);
                v[r] = cmulc(S[PHYS(base + r * SUB)], wc);
            }
            dft16<1>(v);
#pragma unroll
            for (int m = 0; m < 16; m++)
                S[PHYS(base + m * SUB)] = v[((m & 3) << 2) | (m >> 2)];
        }
    }
}

// final (fwd) / first (inv) radix-4 pass on contiguous blocks of 4, no twiddles.
template<int INV>
__device__ __forceinline__ void pass4x(float2* S) {
#pragma unroll
    for (int q = 0; q < 8; q++) {
        int b = threadIdx.x + q * NT;          // quad index in [0, 4096)
        int base = b * 4;
        float2 a = S[PHYS(base)], bb = S[PHYS(base + 1)], c = S[PHYS(base + 2)], d = S[PHYS(base + 3)];
        dft4<INV>(a, bb, c, d);
        S[PHYS(base)] = a; S[PHYS(base + 1)] = bb; S[PHYS(base + 2)] = c; S[PHYS(base + 3)] = d;
    }
}

__device__ __forceinline__ void fwd_fft(float2* S) {
    pass16<1024, 1, 0>(S);  __syncthreads();
    pass16<64, 16, 0>(S);   __syncthreads();
    pass16<4, 256, 0>(S);   __syncthreads();
    pass4x<0>(S);           __syncthreads();
}
__device__ __forceinline__ void inv_fft(float2* S) {
    pass4x<1>(S);           __syncthreads();
    pass16<4, 256, 1>(S);   __syncthreads();
    pass16<64, 16, 1>(S);   __syncthreads();
    pass16<1024, 1, 1>(S);  __syncthreads();
}

// ---------------------------------------------------------------- reductions
__device__ __forceinline__ double blockReduceSumD(double v, double* s) {
    for (int o = 16; o > 0; o >>= 1) v += __shfl_down_sync(0xffffffffu, v, o);
    int lane = threadIdx.x & 31, w = threadIdx.x >> 5;
    __syncthreads();
    if (lane == 0) s[w] = v;
    __syncthreads();
    if (threadIdx.x == 0) {
        int nw = blockDim.x >> 5;
        double r = s[0];
        for (int i = 1; i < nw; i++) r += s[i];
        v = r;
    }
    return v;  // valid on thread 0
}
__device__ __forceinline__ float blockMinAll(float v, float* s) {
    for (int o = 16; o > 0; o >>= 1) v = fminf(v, __shfl_down_sync(0xffffffffu, v, o));
    int lane = threadIdx.x & 31, w = threadIdx.x >> 5;
    __syncthreads();
    if (lane == 0) s[w] = v;
    __syncthreads();
    if (threadIdx.x == 0) {
        int nw = blockDim.x >> 5;
        float r = s[0];
        for (int i = 1; i < nw; i++) r = fminf(r, s[i]);
        s[0] = r;
    }
    __syncthreads();
    float r = s[0];
    __syncthreads();
    return r;
}
__device__ __forceinline__ float blockMaxAll(float v, float* s) {
    for (int o = 16; o > 0; o >>= 1) v = fmaxf(v, __shfl_down_sync(0xffffffffu, v, o));
    int lane = threadIdx.x & 31, w = threadIdx.x >> 5;
    __syncthreads();
    if (lane == 0) s[w] = v;
    __syncthreads();
    if (threadIdx.x == 0) {
        int nw = blockDim.x >> 5;
        float r = s[0];
        for (int i = 1; i < nw; i++) r = fmaxf(r, s[i]);
        s[0] = r;
    }
    __syncthreads();
    float r = s[0];
    __syncthreads();
    return r;
}

// ---------------------------------------------------------------- Hermitian unpack
// From Z = FFT(x + i*y) in the DIF-permuted layout: recover X[j], T[j] for any j.
__device__ __forceinline__ void unpackXT(const float2* S, int j, float2& X, float2& T) {
    j &= (NFFT - 1);
    int jm = (NFFT - j) & (NFFT - 1);
    float2 Zk = S[PHYS(LOCF(j))];
    float2 Zm = S[PHYS(LOCF(jm))];
    X = make_float2(0.5f * (Zk.x + Zm.x), 0.5f * (Zk.y - Zm.y));
    T = make_float2(0.5f * (Zk.y + Zm.y), 0.5f * (Zm.x - Zk.x));
}

// ---------------------------------------------------------------- fused kernel
extern __shared__ float2 sdata[];

__global__ void __launch_bounds__(NT, 1)
fused_kernel(const float* __restrict__ pred, const float* __restrict__ targ,
             const int* __restrict__ ip) {
    __shared__ double red[32];
    __shared__ float sred[32];
    __shared__ int hist[100];
    __shared__ float sv[NT / 32];
    __shared__ int si[NT / 32];

    int row = blockIdx.x;
    const float* xg = pred + (size_t)ip[0] * BROWS * NFFT + (size_t)row * NFFT;
    const float* yg = targ + (size_t)row * NFFT;
    int tid = threadIdx.x;

    // ===== Phase A: load; pearson partials + min/max; z=(x,y) -> smem =====
    float fsx = 0, fsy = 0, fsxy = 0, fsx2 = 0, fsy2 = 0;
    float xmn = 1e30f, xmx = -1e30f, ymn = 1e30f, ymx = -1e30f;
#pragma unroll
    for (int k = 0; k < EPT; k++) {
        int n = tid + k * NT;
        float a = xg[n], b = yg[n];
        fsx += a; fsy += b; fsxy += a * b; fsx2 += a * a; fsy2 += b * b;
        xmn = fminf(xmn, a); xmx = fmaxf(xmx, a);
        ymn = fminf(ymn, b); ymx = fmaxf(ymx, b);
        sdata[PHYS(n)] = make_float2(a, b);
    }
    if (tid < 100) hist[tid] = 0;

    // pearson
    double rsx  = blockReduceSumD(fsx, red);
    double rsy  = blockReduceSumD(fsy, red);
    double rsxy = blockReduceSumD(fsxy, red);
    double rsx2 = blockReduceSumD(fsx2, red);
    double rsy2 = blockReduceSumD(fsy2, red);
    if (tid == 0) {
        double Nd = (double)NFFT;
        double num = Nd * rsxy - rsx * rsy;
        double den = sqrt((Nd * rsx2 - rsx * rsx) * (Nd * rsy2 - rsy * rsy));
        atomicAdd(&g_acc[0], 1.0 - num / den);
    }

    // ===== Phase B: MI histogram (x,y reloaded from L2-hot global) + NMI tail =====
    xmn = blockMinAll(xmn, sred);
    xmx = blockMaxAll(xmx, sred);
    ymn = blockMinAll(ymn, sred);
    ymx = blockMaxAll(ymx, sred);
    float bwx = (xmx - xmn) / 10.0f;
    float bwy = (ymx - ymn) / 10.0f;
#pragma unroll 4
    for (int k = 0; k < EPT; k++) {
        int n = tid + k * NT;
        int ix = min(max((int)((xg[n] - xmn) / bwx), 0), 9);
        int iy = min(max((int)((yg[n] - ymn) / bwy), 0), 9);
        atomicAdd(&hist[ix * 10 + iy], 1);
    }
    __syncthreads();
    double miT = 0.0, entT = 0.0;
    if (tid < 100) {
        int j = tid / 10, kk = tid % 10;
        const double denom = (double)BROWS * (double)NFFT;
        const double eps = 1e-8;
        double hx = 0, hy = 0;
        for (int c = 0; c < 10; c++) { hx += hist[j * 10 + c]; hy += hist[c * 10 + kk]; }
        double pxy = (double)hist[tid] / denom;
        double px = hx / denom, py = hy / denom;
        miT = pxy * log((pxy + eps) / (px * py + eps));
        if (kk == 0) entT -= px * log(px + eps);   // hxe_j
        if (j == 0)  entT -= py * log(py + eps);   // hye_kk
    }
    double miS  = blockReduceSumD(miT, red);
    double entS = blockReduceSumD(entT, red);
    if (tid == 0) atomicAdd(&g_acc[4], miS / (entS * 0.5));
    __syncthreads();

    // ===== Phase C: ONE forward FFT of z = x + i*y =====
    fwd_fft(sdata);

    // ===== Phase D: gather — power spectrum AND windowed cross-spectrum phase.
    // Hann window (periodic) in frequency: Xw[k] = 0.5 X[k] - 0.25 (X[k-1]+X[k+1]).
    // Thread owns 16 consecutive k = (lane<<8)|(warp<<4)|j  -> sequential reuse of
    // unpacks (2 new LDS per k) and lane bits land in LOCF low bits (<=2-way conflicts).
    int lane = tid & 31, wrp = tid >> 5;
    int kbase = (lane << 8) | (wrp << 4);
    float crk[16], cik[16];
    float la = 0.0f, lt = 0.0f;
    float2 Xm1, Tm1, X0, T0, Xp1, Tp1;
    unpackXT(sdata, kbase - 1, Xm1, Tm1);
    unpackXT(sdata, kbase,     X0,  T0);
#pragma unroll
    for (int j = 0; j < 16; j++) {
        unpackXT(sdata, kbase + j + 1, Xp1, Tp1);
        float xp = X0.x * X0.x + X0.y * X0.y;
        float tp = T0.x * T0.x + T0.y * T0.y;
        la += fabsf(xp - tp);
        lt += tp;
        float2 Xw = make_float2(0.5f * X0.x - 0.25f * (Xm1.x + Xp1.x),
                                0.5f * X0.y - 0.25f * (Xm1.y + Xp1.y));
        float2 Tw = make_float2(0.5f * T0.x - 0.25f * (Tm1.x + Tp1.x),
                                0.5f * T0.y - 0.25f * (Tm1.y + Tp1.y));
        float cr = Xw.x * Tw.x + Xw.y * Tw.y;     // C = Xw * conj(Tw)
        float ci = Xw.y * Tw.x - Xw.x * Tw.y;
        float inv = rsqrtf(cr * cr + ci * ci);
        crk[j] = cr * inv; cik[j] = ci * inv;
        Xm1 = X0; Tm1 = T0; X0 = Xp1; T0 = Tp1;
    }
    float cr8 = 0.0f, ci8 = 0.0f;
    if (tid == 0) {   // Nyquist bin k = 8192
        float2 Xm, Tm, Xc, Tc, Xp, Tp;
        unpackXT(sdata, 8191, Xm, Tm);
        unpackXT(sdata, 8192, Xc, Tc);
        unpackXT(sdata, 8193, Xp, Tp);
        float xp = Xc.x * Xc.x + Xc.y * Xc.y;
        float tp = Tc.x * Tc.x + Tc.y * Tc.y;
        la += fabsf(xp - tp);
        lt += tp;
        float2 Xw = make_float2(0.5f * Xc.x - 0.25f * (Xm.x + Xp.x),
                                0.5f * Xc.y - 0.25f * (Xm.y + Xp.y));
        float2 Tw = make_float2(0.5f * Tc.x - 0.25f * (Tm.x + Tp.x),
                                0.5f * Tc.y - 0.25f * (Tm.y + Tp.y));
        float cr = Xw.x * Tw.x + Xw.y * Tw.y;
        float ci = Xw.y * Tw.x - Xw.x * Tw.y;
        float inv = rsqrtf(cr * cr + ci * ci);
        cr8 = cr * inv; ci8 = ci * inv;
    }
    double ba = blockReduceSumD((double)la, red);
    double bt = blockReduceSumD((double)lt, red);
    if (tid == 0) { atomicAdd(&g_acc[2], ba); atomicAdd(&g_acc[3], bt); }
    __syncthreads();    // all gathers done -> safe to overwrite sdata

    // write Chat (full Hermitian spectrum) into the permuted layout for inv_fft
#pragma unroll
    for (int j = 0; j < 16; j++) {
        int k = kbase + j;
        int pk = PHYS(LOCF(k));
        int pm = PHYS(LOCF((NFFT - k) & (NFFT - 1)));
        sdata[pk] = make_float2(crk[j], cik[j]);
        if (pm != pk) sdata[pm] = make_float2(crk[j], -cik[j]);
    }
    if (tid == 0) sdata[PHYS(LOCF(8192))] = make_float2(cr8, ci8);
    __syncthreads();

    // ===== Phase E: inverse FFT -> natural order; 1/N scale irrelevant for argmax =====
    inv_fft(sdata);

    // ===== Phase F: argmax of real part =====
    float bv = -1e30f; int bi = 0;
#pragma unroll
    for (int k = 0; k < EPT; k++) {
        int n = tid + k * NT;
        float v = sdata[PHYS(n)].x;
        if (v > bv) { bv = v; bi = n; }
    }
    for (int o = 16; o > 0; o >>= 1) {
        float ov = __shfl_down_sync(0xffffffffu, bv, o);
        int   oi = __shfl_down_sync(0xffffffffu, bi, o);
        if (ov > bv || (ov == bv && oi < bi)) { bv = ov; bi = oi; }
    }
    if (lane == 0) { sv[wrp] = bv; si[wrp] = bi; }
    __syncthreads();
    if (tid == 0) {
        for (int iw = 1; iw < NT / 32; iw++)
            if (sv[iw] > bv || (sv[iw] == bv && si[iw] < bi)) { bv = sv[iw]; bi = si[iw]; }
        atomicAdd(&g_acc[1], cospi(2.0 * (double)bi / (double)NFFT));
    }
}

// ---------------------------------------------------------------- finalize
__global__ void finalize_kernel(const int* __restrict__ ep, float* __restrict__ out) {
    double loss = g_acc[0] / (double)BROWS;          // neg pearson
    int epoch = ep[0];
    if (epoch >= 400) {
        loss += 1.0 - g_acc[1] / (double)BROWS;      // phase correlation
        loss += g_acc[2] / g_acc[3];                 // power spectrum
    }
    if (epoch >= 700) {
        loss += 1.0 - g_acc[4] / (double)BROWS;      // mutual information
    }
    out[0] = (float)loss;
}

// ---------------------------------------------------------------- launch
extern "C" void kernel_launch(void* const* d_in, const int* in_sizes, int n_in,
                              void* d_out, int out_size) {
    const float* pred = (const float*)d_in[0];   // [2, 512, 16384] f32
    const float* targ = (const float*)d_in[1];   // [512, 16384] f32
    const int* ip = (const int*)d_in[2];         // scalar i
    const int* ep = (const int*)d_in[3];         // scalar epoch
    float* out = (float*)d_out;

    cudaFuncSetAttribute(fused_kernel,
                         cudaFuncAttributeMaxDynamicSharedMemorySize,
                         NFFT * (int)sizeof(float2));

    init_kernel<<<64, 256>>>();
    fused_kernel<<<BROWS, NT, NFFT * sizeof(float2)>>>(pred, targ, ip);
    finalize_kernel<<<1, 1>>>(ep, out);
}